// round 11
// baseline (speedup 1.0000x reference)
#include <cuda_runtime.h>
#include <cstdint>

#define B_ 512
#define T_ 256
#define H_ 128
typedef unsigned long long ull;

// scratch: layer-1 hidden sequence (T, B, H) + final h of layer 2
__device__ float g_h0[(size_t)T_ * B_ * H_];
__device__ float g_last[B_ * H_];

// packed fp32x2 FMA: d = a * b + d
#define FMA2(d, a, b) asm("fma.rn.f32x2 %0, %1, %2, %0;" : "+l"(d) : "l"(a), "l"(b))
// duplicate a float into both halves of a 64-bit reg
#define DUP2(d, f)    asm("mov.b64 %0, {%1, %1};" : "=l"(d) : "f"(f))

__device__ __forceinline__ void st_peer_f32(uint32_t laddr, int peer, float v) {
    uint32_t ra;
    asm volatile("mapa.shared::cluster.u32 %0, %1, %2;" : "=r"(ra) : "r"(laddr), "r"(peer));
    asm volatile("st.shared::cluster.f32 [%0], %1;" :: "r"(ra), "f"(v) : "memory");
}
__device__ __forceinline__ void cluster_arrive_() {
    asm volatile("barrier.cluster.arrive.aligned;" ::: "memory");
}
__device__ __forceinline__ void cluster_wait_() {
    asm volatile("barrier.cluster.wait.aligned;" ::: "memory");
}

__device__ __forceinline__ float sigmoid_(float x) { return 1.f / (1.f + __expf(-x)); }
__device__ __forceinline__ float tanh_(float x)    { return 2.f / (1.f + __expf(-2.f * x)) - 1.f; }

// Fused LSTM layer. Cluster of 4 CTAs, 16 batch per cluster; CTA rank r owns
// h-dims [r*32, r*32+32) (gate rows g*128 + r*32 + d).
// 512 threads, 16 warps: K-split-8 x batch-split-2 (warp = kg*2+bg).
// Per-thread tile = 8 batches x (4 gates of d=lane). v rows PLAIN 16 floats
// (stride VS=20). Batch-packed f32x2 accumulators; w duplicated per-k via MOV.
template <int KIN, bool IN_TB, bool WRITE_SEQ>
__global__ void __cluster_dims__(4, 1, 1) __launch_bounds__(512, 1)
lstm_layer(const float* __restrict__ in,
           const float* __restrict__ w_ih, const float* __restrict__ w_hh,
           const float* __restrict__ b_ih, const float* __restrict__ b_hh,
           float* __restrict__ out_seq, float* __restrict__ out_last)
{
    constexpr int  KTOT  = KIN + H_;
    constexpr int  KQ    = KTOT / 8;         // per-K-slice range
    constexpr bool SPLIT = (KIN == H_);      // layer-2 memory layout
    constexpr int  VS    = 20;               // v row stride: 16 floats + pad

    extern __shared__ float smem[];
    float* w_s    = smem;                                  // [KTOT][128]
    float* v_in   = w_s + KTOT * 128;                      // SPLIT: [KIN][VS] single
    float* vh0    = SPLIT ? (v_in + KIN * VS) : v_in;      // SPLIT: [128][VS] h buf0
    float* vh1    = vh0 + (SPLIT ? H_ : KTOT) * VS;        // buf1 (or full buffer 1)
    float* g_s    = vh1 + (SPLIT ? H_ : KTOT) * VS;        // [16 slices][16][64]
    float* bias_s = g_s + 16384;                           // [128]
    float* c_s    = bias_s + 128;                          // [16][32]

    const int tid    = threadIdx.x;
    const int rank   = blockIdx.x & 3;
    const int b_base = (blockIdx.x >> 2) * 16;

    // ---- weights into SMEM: w_s[k][col], col = gate*32 + d ----
    for (int idx = tid; idx < 128 * KIN; idx += 512) {
        int col = idx / KIN, k = idx % KIN;
        int grow = (col >> 5) * 128 + rank * 32 + (col & 31);
        w_s[k * 128 + col] = w_ih[grow * KIN + k];
    }
    for (int idx = tid; idx < 128 * H_; idx += 512) {
        int col = idx / H_, k = idx % H_;
        int grow = (col >> 5) * 128 + rank * 32 + (col & 31);
        w_s[(KIN + k) * 128 + col] = w_hh[grow * H_ + k];
    }
    if (tid < 128) {
        int grow = (tid >> 5) * 128 + rank * 32 + (tid & 31);
        bias_s[tid] = b_ih[grow] + b_hh[grow];
    }
    if (tid < 512) c_s[tid] = 0.f;
    {   // zero h(-1) rows of buffer 0
        float* hz = SPLIT ? vh0 : (v_in + KIN * VS);
        for (int idx = tid; idx < H_ * 16; idx += 512)
            hz[(idx >> 4) * VS + (idx & 15)] = 0.f;
    }
    // ---- stage t=0 input ----
    if (IN_TB) {  // (T,B,128): thread -> one k, 4 batches
        int k = tid & 127, bq = (tid >> 7) * 4;
        const float* src = in + ((size_t)0 * B_ + b_base + bq) * KIN + k;
        #pragma unroll
        for (int i = 0; i < 4; ++i)
            v_in[k * VS + bq + i] = src[(size_t)i * KIN];
    } else {      // (B,T,32): 1 float per thread
        int b = tid >> 5, k = tid & 31;
        v_in[k * VS + b] = in[((size_t)(b_base + b) * T_ + 0) * KIN + k];
    }
    __syncthreads();
    cluster_arrive_(); cluster_wait_();

    // ---- GEMM thread mapping ----
    const int lane = tid & 31;
    const int warp = tid >> 5;
    const int kg   = warp >> 1;          // K slice (0..7)
    const int bg   = warp & 1;           // batch half (8 batches)
    const int b0   = bg * 8;
    const int kbeg = kg * KQ;
    float* gslice = g_s + ((kg * 2 + bg) * 16) * 64;   // + (bp*4+gate)*64

    // pointwise mapping: exactly one (b,d) pair per thread
    const int pb = tid >> 5, pd = tid & 31;
    const int bg2 = pb >> 3, bp2 = (pb >> 1) & 3, par = pb & 1;

    for (int t = 0; t < T_; ++t) {
        // ---- prefetch next-step input into registers ----
        float pf[4];
        float pf1 = 0.f;
        if (t + 1 < T_) {
            if (IN_TB) {
                int k = tid & 127, bq = (tid >> 7) * 4;
                const float* src = in + ((size_t)(t + 1) * B_ + b_base + bq) * KIN + k;
                #pragma unroll
                for (int i = 0; i < 4; ++i) pf[i] = src[(size_t)i * KIN];
            } else {
                pf1 = in[((size_t)(b_base + pb) * T_ + (t + 1)) * KIN + pd];
            }
        }

        // ---- GEMM over my K slice: acc[gate][bp] (4 gates of d=lane, 8 batches) ----
        const float* vbase;
        if (SPLIT) vbase = (kg < 4) ? (v_in + kbeg * VS)
                                    : (((t & 1) ? vh1 : vh0) + (kbeg - KIN) * VS);
        else       vbase = (((t & 1) ? vh1 : v_in)) + kbeg * VS;
        const float* wbase = w_s + kbeg * 128 + lane;

        ull acc[4][4];
        #pragma unroll
        for (int g = 0; g < 4; ++g)
            #pragma unroll
            for (int bp = 0; bp < 4; ++bp) acc[g][bp] = 0ull;

        #pragma unroll 4
        for (int kk = 0; kk < KQ; ++kk) {
            const float* vr = vbase + kk * VS + b0;
            ulonglong2 va = *(const ulonglong2*)vr;        // (b0,b1),(b2,b3)
            ulonglong2 vb = *(const ulonglong2*)(vr + 4);  // (b4,b5),(b6,b7)
            const float* wr = wbase + kk * 128;
            float w0 = wr[0], w1 = wr[32], w2 = wr[64], w3 = wr[96];
            ull d0, d1, d2, d3;
            DUP2(d0, w0); DUP2(d1, w1); DUP2(d2, w2); DUP2(d3, w3);
            FMA2(acc[0][0], va.x, d0); FMA2(acc[0][1], va.y, d0);
            FMA2(acc[0][2], vb.x, d0); FMA2(acc[0][3], vb.y, d0);
            FMA2(acc[1][0], va.x, d1); FMA2(acc[1][1], va.y, d1);
            FMA2(acc[1][2], vb.x, d1); FMA2(acc[1][3], vb.y, d1);
            FMA2(acc[2][0], va.x, d2); FMA2(acc[2][1], va.y, d2);
            FMA2(acc[2][2], vb.x, d2); FMA2(acc[2][3], vb.y, d2);
            FMA2(acc[3][0], va.x, d3); FMA2(acc[3][1], va.y, d3);
            FMA2(acc[3][2], vb.x, d3); FMA2(acc[3][3], vb.y, d3);
        }

        // ---- store K-slice partials: STS.64, lane-contiguous (no conflicts) ----
        #pragma unroll
        for (int bp = 0; bp < 4; ++bp)
            #pragma unroll
            for (int g = 0; g < 4; ++g)
                *(ull*)(gslice + (bp * 4 + g) * 64 + lane * 2) = acc[g][bp];
        __syncthreads();

        // ---- pointwise gates + h broadcast: one (b,d) pair per thread ----
        {
            float gv[4];
            #pragma unroll
            for (int g = 0; g < 4; ++g) {
                float s = bias_s[g * 32 + pd];
                #pragma unroll
                for (int sl = 0; sl < 8; ++sl)
                    s += g_s[((sl * 2 + bg2) * 16 + bp2 * 4 + g) * 64 + pd * 2 + par];
                gv[g] = s;
            }
            float is = sigmoid_(gv[0]);
            float fs = sigmoid_(gv[1]);
            float gt = tanh_(gv[2]);
            float os = sigmoid_(gv[3]);
            float c  = fs * c_s[pb * 32 + pd] + is * gt;
            c_s[pb * 32 + pd] = c;
            float h  = os * tanh_(c);

            float* hrow = SPLIT ? (((t & 1) ? vh0 : vh1) + (rank * 32 + pd) * VS)
                                : (((t & 1) ? v_in : vh1) + (KIN + rank * 32 + pd) * VS);
            float* dst = hrow + pb;
            *dst = h;
            uint32_t la = (uint32_t)__cvta_generic_to_shared(dst);
            if (rank != 0) st_peer_f32(la, 0, h);
            if (rank != 1) st_peer_f32(la, 1, h);
            if (rank != 2) st_peer_f32(la, 2, h);
            if (rank != 3) st_peer_f32(la, 3, h);

            if (WRITE_SEQ) {
                out_seq[((size_t)t * B_ + (b_base + pb)) * H_ + rank * 32 + pd] = h;
            } else if (t == T_ - 1) {
                out_last[(size_t)(b_base + pb) * H_ + rank * 32 + pd] = h;
            }
        }

        // release my h-slice; overlap local input staging with cluster latency
        cluster_arrive_();
        if (t + 1 < T_) {
            if (IN_TB) {
                int k = tid & 127, bq = (tid >> 7) * 4;
                #pragma unroll
                for (int i = 0; i < 4; ++i)
                    v_in[k * VS + bq + i] = pf[i];
            } else {
                float* vn = (t & 1) ? v_in : vh1;   // next step's buffer
                vn[pd * VS + pb] = pf1;
            }
        }
        cluster_wait_();
    }
}

// FC head: out[b] = fc2_b + sum_j fc2_w[j] * relu(fc1_b[j] + h1_last[b] . fc1_w[j])
__global__ void __launch_bounds__(64) fc_head(
    const float* __restrict__ last_h,
    const float* __restrict__ fc1_w, const float* __restrict__ fc1_b,
    const float* __restrict__ fc2_w, const float* __restrict__ fc2_b,
    float* __restrict__ out)
{
    int b = blockIdx.x, j = threadIdx.x;
    const float* h = last_h + (size_t)b * H_;
    const float* w = fc1_w + (size_t)j * H_;
    float s = fc1_b[j];
    #pragma unroll 8
    for (int k = 0; k < H_; ++k) s = fmaf(h[k], w[k], s);
    float z = fmaxf(s, 0.f) * fc2_w[j];

    __shared__ float red[2];
    #pragma unroll
    for (int o = 16; o > 0; o >>= 1) z += __shfl_down_sync(0xffffffff, z, o);
    if ((j & 31) == 0) red[j >> 5] = z;
    __syncthreads();
    if (j == 0) out[b] = red[0] + red[1] + fc2_b[0];
}

extern "C" void kernel_launch(void* const* d_in, const int* in_sizes, int n_in,
                              void* d_out, int out_size)
{
    const float* x     = (const float*)d_in[0];
    const float* w_ih0 = (const float*)d_in[1];
    const float* w_hh0 = (const float*)d_in[2];
    const float* b_ih0 = (const float*)d_in[3];
    const float* b_hh0 = (const float*)d_in[4];
    const float* w_ih1 = (const float*)d_in[5];
    const float* w_hh1 = (const float*)d_in[6];
    const float* b_ih1 = (const float*)d_in[7];
    const float* b_hh1 = (const float*)d_in[8];
    const float* fc1_w = (const float*)d_in[9];
    const float* fc1_b = (const float*)d_in[10];
    const float* fc2_w = (const float*)d_in[11];
    const float* fc2_b = (const float*)d_in[12];
    float* out = (float*)d_out;

    float *h0_ptr, *last_ptr;
    cudaGetSymbolAddress((void**)&h0_ptr, g_h0);
    cudaGetSymbolAddress((void**)&last_ptr, g_last);

    // layer1: w 160*128 + v 2*160*20 + g 16384 + bias 128 + c 512
    constexpr int SMEM1 = (160 * 128 + 2 * 160 * 20 + 16384 + 128 + 512) * 4;  // 175,616
    // layer2: w 256*128 + v 3*128*20 + g 16384 + bias 128 + c 512
    constexpr int SMEM2 = (256 * 128 + 3 * 128 * 20 + 16384 + 128 + 512) * 4;  // 229,888

    cudaFuncSetAttribute(lstm_layer<32, false, true>,
                         cudaFuncAttributeMaxDynamicSharedMemorySize, SMEM1);
    cudaFuncSetAttribute(lstm_layer<128, true, false>,
                         cudaFuncAttributeMaxDynamicSharedMemorySize, SMEM2);

    lstm_layer<32, false, true><<<128, 512, SMEM1>>>(
        x, w_ih0, w_hh0, b_ih0, b_hh0, h0_ptr, nullptr);
    lstm_layer<128, true, false><<<128, 512, SMEM2>>>(
        h0_ptr, w_ih1, w_hh1, b_ih1, b_hh1, nullptr, last_ptr);
    fc_head<<<B_, 64>>>(last_ptr, fc1_w, fc1_b, fc2_w, fc2_b, out);

    (void)in_sizes; (void)n_in; (void)out_size;
}